// round 5
// baseline (speedup 1.0000x reference)
#include <cuda_runtime.h>
#include <math.h>

// ---------------------------------------------------------------------------
// EncoderLayer: RES=12000 residues, K=48 neighbors, H=128 hidden.
//
// Decomposition:
//   concat(h_i,h_j,e) @ W0  ==  h_i@W0a + h_j@W0b + e@W0c
//   and h_j@W0b == (node@W0b)[edge_idx]   (project-then-gather)
//
// R5 change vs R3: mm48 inner loop rebuilt to fix the smem-crossbar bottleneck
//   - thread owns 4 CONTIGUOUS output cols (4tx..4tx+3)  -> w via one LDS.128
//   - k unrolled by 4 -> x row scalars fetched as one LDS.128 broadcast per row
//   crossbar cycles/SM/4k: 320 -> 176, now below the 192 fma-pipe cycles.
// ---------------------------------------------------------------------------

#define RES   12000
#define KN    48
#define H     128
#define HH    (H*H)            // 16384 floats
#define TILE_FLOATS (KN*H)     // 6144 floats
#define NTHREADS 256

typedef unsigned long long u64;

// Scratch (no cudaMalloc allowed; __device__ globals are the sanctioned path)
__device__ float g_PA1[RES*H];
__device__ float g_PB1[RES*H];
__device__ float g_PA2[RES*H];
__device__ float g_PB2[RES*H];
__device__ float g_NODE1[RES*H];
__device__ float g_FFH[(size_t)RES*4*H];

// ---------------- packed f32x2 helpers (Blackwell sm_103a) -----------------
__device__ __forceinline__ u64 pk2(float x){
    u64 r; asm("mov.b64 %0, {%1, %1};" : "=l"(r) : "f"(x)); return r;
}
__device__ __forceinline__ u64 pk(float lo, float hi){
    u64 r; asm("mov.b64 %0, {%1, %2};" : "=l"(r) : "f"(lo), "f"(hi)); return r;
}
__device__ __forceinline__ u64 fma2(u64 a, u64 b, u64 c){
    u64 d; asm("fma.rn.f32x2 %0, %1, %2, %3;" : "=l"(d) : "l"(a), "l"(b), "l"(c)); return d;
}
__device__ __forceinline__ float2 up2(u64 v){
    float lo, hi; asm("mov.b64 {%0, %1}, %2;" : "=f"(lo), "=f"(hi) : "l"(v));
    return make_float2(lo, hi);
}
__device__ __forceinline__ float gelu(float x){
    // exact-erf GELU (reference uses approximate=False)
    return 0.5f * x * (1.0f + erff(x * 0.7071067811865475f));
}

// 48x128 += 48x128 @ 128x128, xs/ws in smem (both natural row-major).
// thread (tx,ty): rows m = ty*6 .. ty*6+5 ; cols 4tx..4tx+3
// acc[2r] = col pair (4tx,4tx+1) of row r ; acc[2r+1] = pair (4tx+2,4tx+3)
__device__ __forceinline__ void mm48(const float* __restrict__ xs,
                                     const float* __restrict__ ws,
                                     int tx, int ty, u64 acc[12]){
    const float* xr = xs + ty*6*H;
    const float4* wp = (const float4*)ws;
    #pragma unroll 2
    for (int k = 0; k < H; k += 4){
        // x: one LDS.128 broadcast per row covers 4 k-steps
        float4 xv0 = *(const float4*)(xr + 0*H + k);
        float4 xv1 = *(const float4*)(xr + 1*H + k);
        float4 xv2 = *(const float4*)(xr + 2*H + k);
        float4 xv3 = *(const float4*)(xr + 3*H + k);
        float4 xv4 = *(const float4*)(xr + 4*H + k);
        float4 xv5 = *(const float4*)(xr + 5*H + k);
        // w: one LDS.128 per k-step (thread's 4 contiguous cols)
        float4 wk0 = wp[(k+0)*(H/4) + tx];
        float4 wk1 = wp[(k+1)*(H/4) + tx];
        float4 wk2 = wp[(k+2)*(H/4) + tx];
        float4 wk3 = wp[(k+3)*(H/4) + tx];

#define MM48_STEP(WK, COMP)                                                    \
        {                                                                      \
            u64 wl = pk(WK.x, WK.y), wh = pk(WK.z, WK.w);                      \
            u64 a0 = pk2(xv0.COMP); acc[0]  = fma2(a0, wl, acc[0]);            \
                                    acc[1]  = fma2(a0, wh, acc[1]);            \
            u64 a1 = pk2(xv1.COMP); acc[2]  = fma2(a1, wl, acc[2]);            \
                                    acc[3]  = fma2(a1, wh, acc[3]);            \
            u64 a2 = pk2(xv2.COMP); acc[4]  = fma2(a2, wl, acc[4]);            \
                                    acc[5]  = fma2(a2, wh, acc[5]);            \
            u64 a3 = pk2(xv3.COMP); acc[6]  = fma2(a3, wl, acc[6]);            \
                                    acc[7]  = fma2(a3, wh, acc[7]);            \
            u64 a4 = pk2(xv4.COMP); acc[8]  = fma2(a4, wl, acc[8]);            \
                                    acc[9]  = fma2(a4, wh, acc[9]);            \
            u64 a5 = pk2(xv5.COMP); acc[10] = fma2(a5, wl, acc[10]);           \
                                    acc[11] = fma2(a5, wh, acc[11]);           \
        }
        MM48_STEP(wk0, x)
        MM48_STEP(wk1, y)
        MM48_STEP(wk2, z)
        MM48_STEP(wk3, w)
#undef MM48_STEP
    }
}

__device__ __forceinline__ void copy16k(float* dst, const float* src, int tid){
    const float4* s = (const float4*)src; float4* d = (float4*)dst;
    #pragma unroll 4
    for (int i = tid; i < HH/4; i += NTHREADS) d[i] = s[i];
}
__device__ __forceinline__ void copytile(float* dst, const float* src, int tid){
    const float4* s = (const float4*)src; float4* d = (float4*)dst;
    #pragma unroll
    for (int i = tid; i < TILE_FLOATS/4; i += NTHREADS) d[i] = s[i];
}

// ------------------------- proj: out = src@W (+bias) -----------------------
__global__ void __launch_bounds__(NTHREADS)
proj_kernel(const float* __restrict__ src, const float* __restrict__ w,
            const float* __restrict__ bias, int sel){
    extern __shared__ float sm[];
    float* ws = sm; float* xs = sm + HH;
    int tid = threadIdx.x, tx = tid & 31, ty = tid >> 5;
    copy16k(ws, w, tid);
    copytile(xs, src + (size_t)blockIdx.x*TILE_FLOATS, tid);
    __syncthreads();
    u64 acc[12];
    #pragma unroll
    for (int q = 0; q < 12; q++) acc[q] = 0ull;
    mm48(xs, ws, tx, ty, acc);
    float4 bv = make_float4(0.f,0.f,0.f,0.f);
    if (bias) bv = *(const float4*)(bias + 4*tx);
    float* outp = (sel==0) ? g_PA1 : (sel==1) ? g_PB1 : (sel==2) ? g_PA2 : g_PB2;
    int base = blockIdx.x * KN;
    #pragma unroll
    for (int r = 0; r < 6; r++){
        int m = ty*6 + r;
        float2 v0 = up2(acc[2*r]), v1 = up2(acc[2*r+1]);
        *(float4*)(outp + (size_t)(base+m)*H + 4*tx) =
            make_float4(v0.x+bv.x, v0.y+bv.y, v1.x+bv.z, v1.y+bv.w);
    }
}

// --------------------- message pass + k-sum + LN1 --------------------------
__global__ void __launch_bounds__(NTHREADS)
msg_kernel(const float* __restrict__ node_h, const float* __restrict__ edge_h,
           const float* __restrict__ w0c, const float* __restrict__ w1,
           const float* __restrict__ b1,  const float* __restrict__ w2,
           const float* __restrict__ b2,  const float* __restrict__ ln1_g,
           const float* __restrict__ ln1_b, const int* __restrict__ edge_idx){
    extern __shared__ float sm[];
    float* ws0 = sm; float* ws1 = sm + HH; float* ws2 = sm + 2*HH;
    float* xs  = sm + 3*HH;                       // TILE_FLOATS, also reduction scratch
    int tid = threadIdx.x, tx = tid & 31, ty = tid >> 5;

    copy16k(ws0, w0c, tid);
    copy16k(ws1, w1, tid);
    copy16k(ws2, w2, tid);
    float4 b1v = *(const float4*)(b1 + 4*tx);
    float lg=0.f, lb=0.f, b2t=0.f;
    if (tid < H){ lg=ln1_g[tid]; lb=ln1_b[tid]; b2t=b2[tid]; }
    __syncthreads();

    for (int i = blockIdx.x; i < RES; i += gridDim.x){
        copytile(xs, edge_h + (size_t)i*TILE_FLOATS, tid);
        int jr[6];
        #pragma unroll
        for (int r = 0; r < 6; r++) jr[r] = edge_idx[i*KN + ty*6 + r];
        __syncthreads();

        // layer 0: y0 = e@W0c + PA1[i] + PB1[j] ; x1 = gelu(y0)
        u64 acc[12];
        #pragma unroll
        for (int q = 0; q < 12; q++) acc[q] = 0ull;
        mm48(xs, ws0, tx, ty, acc);
        float4 pa = *(const float4*)(g_PA1 + (size_t)i*H + 4*tx);
        __syncthreads();
        #pragma unroll
        for (int r = 0; r < 6; r++){
            float4 pb = *(const float4*)(g_PB1 + (size_t)jr[r]*H + 4*tx);
            float2 v0 = up2(acc[2*r]), v1 = up2(acc[2*r+1]);
            *(float4*)(xs + (ty*6+r)*H + 4*tx) =
                make_float4(gelu(v0.x+pa.x+pb.x), gelu(v0.y+pa.y+pb.y),
                            gelu(v1.x+pa.z+pb.z), gelu(v1.y+pa.w+pb.w));
        }
        __syncthreads();

        // layer 1: x2 = gelu(x1@W1 + b1)
        #pragma unroll
        for (int q = 0; q < 12; q++) acc[q] = 0ull;
        mm48(xs, ws1, tx, ty, acc);
        __syncthreads();
        #pragma unroll
        for (int r = 0; r < 6; r++){
            float2 v0 = up2(acc[2*r]), v1 = up2(acc[2*r+1]);
            *(float4*)(xs + (ty*6+r)*H + 4*tx) =
                make_float4(gelu(v0.x+b1v.x), gelu(v0.y+b1v.y),
                            gelu(v1.x+b1v.z), gelu(v1.y+b1v.w));
        }
        __syncthreads();

        // layer 2: y2 = x2@W2 (+b2 folded into the k-sum as 48*b2)
        #pragma unroll
        for (int q = 0; q < 12; q++) acc[q] = 0ull;
        mm48(xs, ws2, tx, ty, acc);
        float c0=0.f, c1=0.f, c2=0.f, c3=0.f;
        #pragma unroll
        for (int r = 0; r < 6; r++){
            float2 v0 = up2(acc[2*r]), v1 = up2(acc[2*r+1]);
            c0 += v0.x; c1 += v0.y; c2 += v1.x; c3 += v1.y;
        }
        __syncthreads();                       // xs reads done -> reuse as scratch
        *(float4*)(xs + ty*H + 4*tx) = make_float4(c0, c1, c2, c3);
        __syncthreads();
        float v = 0.f;
        if (tid < H){
            float s = 0.f;
            #pragma unroll
            for (int t = 0; t < 8; t++) s += xs[t*H + tid];
            v = node_h[(size_t)i*H + tid] + s + 48.0f*b2t;
            xs[1024 + tid] = v;
        }
        __syncthreads();
        if (tid < 32){
            float s = 0.f, q = 0.f;
            #pragma unroll
            for (int g = 0; g < 4; g++){ float t = xs[1024 + tid + 32*g]; s += t; q += t*t; }
            #pragma unroll
            for (int off = 16; off; off >>= 1){
                s += __shfl_xor_sync(0xffffffffu, s, off);
                q += __shfl_xor_sync(0xffffffffu, q, off);
            }
            if (tid == 0){
                float mean = s * (1.0f/H);
                float var  = q * (1.0f/H) - mean*mean;
                xs[1152] = mean;
                xs[1153] = rsqrtf(var + 1e-5f);
            }
        }
        __syncthreads();
        if (tid < H){
            g_NODE1[(size_t)i*H + tid] = (v - xs[1152]) * xs[1153] * lg + lb;
        }
        __syncthreads();                       // protect xs before next iteration
    }
}

// ----------------------- FF part 1: FFH = gelu(N1@W0+b0) -------------------
__global__ void __launch_bounds__(NTHREADS)
ff1_kernel(const float* __restrict__ w, const float* __restrict__ bias){
    extern __shared__ float sm[];
    float* ws = sm; float* xs = sm + HH;
    int tid = threadIdx.x, tx = tid & 31, ty = tid >> 5;
    int n0 = blockIdx.y * H;
    {   // strided copy: w is [128,512] row-major, take column block n0..n0+127
        float4* d = (float4*)ws;
        #pragma unroll 4
        for (int i = tid; i < HH/4; i += NTHREADS){
            int k = i >> 5, c = i & 31;
            d[i] = *(const float4*)(w + (size_t)k*(4*H) + n0 + 4*c);
        }
    }
    copytile(xs, g_NODE1 + (size_t)blockIdx.x*TILE_FLOATS, tid);
    __syncthreads();
    u64 acc[12];
    #pragma unroll
    for (int q = 0; q < 12; q++) acc[q] = 0ull;
    mm48(xs, ws, tx, ty, acc);
    float4 bv = *(const float4*)(bias + n0 + 4*tx);
    int base = blockIdx.x * KN;
    #pragma unroll
    for (int r = 0; r < 6; r++){
        int m = ty*6 + r;
        float2 v0 = up2(acc[2*r]), v1 = up2(acc[2*r+1]);
        *(float4*)(g_FFH + (size_t)(base+m)*(4*H) + n0 + 4*tx) =
            make_float4(gelu(v0.x+bv.x), gelu(v0.y+bv.y),
                        gelu(v1.x+bv.z), gelu(v1.y+bv.w));
    }
}

// ------------- FF part 2: node2 = LN2(N1 + FFH@W1 + b1) -> d_out -----------
__global__ void __launch_bounds__(NTHREADS)
ff2_kernel(const float* __restrict__ w, const float* __restrict__ bias,
           const float* __restrict__ ln2_g, const float* __restrict__ ln2_b,
           float* __restrict__ out_node){
    extern __shared__ float sm[];
    float* ws = sm; float* xs = sm + HH;
    int tid = threadIdx.x, tx = tid & 31, ty = tid >> 5;
    int base = blockIdx.x * KN;
    u64 acc[12];
    #pragma unroll
    for (int q = 0; q < 12; q++) acc[q] = 0ull;
    for (int c = 0; c < 4; c++){
        copy16k(ws, w + (size_t)c*H*H, tid);      // [512,128] rows c*128..c*128+127
        {
            float4* d = (float4*)xs;
            #pragma unroll
            for (int i = tid; i < TILE_FLOATS/4; i += NTHREADS){
                int m = i >> 5, cc = i & 31;
                d[i] = *(const float4*)(g_FFH + (size_t)(base+m)*(4*H) + c*H + 4*cc);
            }
        }
        __syncthreads();
        mm48(xs, ws, tx, ty, acc);
        __syncthreads();
    }
    float4 bv = *(const float4*)(bias + 4*tx);
    float4 lg = *(const float4*)(ln2_g + 4*tx);
    float4 lb = *(const float4*)(ln2_b + 4*tx);
    #pragma unroll
    for (int r = 0; r < 6; r++){
        int row = base + ty*6 + r;
        float4 a = *(const float4*)(g_NODE1 + (size_t)row*H + 4*tx);
        float2 v0 = up2(acc[2*r]), v1 = up2(acc[2*r+1]);
        float x0 = v0.x+bv.x+a.x, x1 = v0.y+bv.y+a.y;
        float x2 = v1.x+bv.z+a.z, x3 = v1.y+bv.w+a.w;
        float s = x0+x1+x2+x3, q = x0*x0+x1*x1+x2*x2+x3*x3;
        #pragma unroll
        for (int off = 16; off; off >>= 1){
            s += __shfl_xor_sync(0xffffffffu, s, off);
            q += __shfl_xor_sync(0xffffffffu, q, off);
        }
        float mean = s * (1.0f/H);
        float rstd = rsqrtf(q*(1.0f/H) - mean*mean + 1e-5f);
        *(float4*)(out_node + (size_t)row*H + 4*tx) =
            make_float4((x0-mean)*rstd*lg.x+lb.x, (x1-mean)*rstd*lg.y+lb.y,
                        (x2-mean)*rstd*lg.z+lb.z, (x3-mean)*rstd*lg.w+lb.w);
    }
}

// -------------------- edge update + LNe -> d_out (edge) --------------------
__global__ void __launch_bounds__(NTHREADS)
edge_kernel(const float* __restrict__ edge_h, const float* __restrict__ w0c,
            const float* __restrict__ w1, const float* __restrict__ b1,
            const float* __restrict__ w2, const float* __restrict__ b2,
            const float* __restrict__ lne_g, const float* __restrict__ lne_b,
            const int* __restrict__ edge_idx, float* __restrict__ out_edge){
    extern __shared__ float sm[];
    float* ws0 = sm; float* ws1 = sm + HH; float* ws2 = sm + 2*HH;
    float* xs  = sm + 3*HH;
    int tid = threadIdx.x, tx = tid & 31, ty = tid >> 5;

    copy16k(ws0, w0c, tid);
    copy16k(ws1, w1, tid);
    copy16k(ws2, w2, tid);
    float4 b1v = *(const float4*)(b1 + 4*tx);
    float4 b2v = *(const float4*)(b2 + 4*tx);
    float4 lg  = *(const float4*)(lne_g + 4*tx);
    float4 lb  = *(const float4*)(lne_b + 4*tx);
    __syncthreads();

    for (int i = blockIdx.x; i < RES; i += gridDim.x){
        copytile(xs, edge_h + (size_t)i*TILE_FLOATS, tid);
        int jr[6];
        #pragma unroll
        for (int r = 0; r < 6; r++) jr[r] = edge_idx[i*KN + ty*6 + r];
        __syncthreads();

        u64 acc[12];
        #pragma unroll
        for (int q = 0; q < 12; q++) acc[q] = 0ull;
        mm48(xs, ws0, tx, ty, acc);
        float4 pa = *(const float4*)(g_PA2 + (size_t)i*H + 4*tx);
        __syncthreads();
        #pragma unroll
        for (int r = 0; r < 6; r++){
            float4 pb = *(const float4*)(g_PB2 + (size_t)jr[r]*H + 4*tx);
            float2 v0 = up2(acc[2*r]), v1 = up2(acc[2*r+1]);
            *(float4*)(xs + (ty*6+r)*H + 4*tx) =
                make_float4(gelu(v0.x+pa.x+pb.x), gelu(v0.y+pa.y+pb.y),
                            gelu(v1.x+pa.z+pb.z), gelu(v1.y+pa.w+pb.w));
        }
        __syncthreads();

        #pragma unroll
        for (int q = 0; q < 12; q++) acc[q] = 0ull;
        mm48(xs, ws1, tx, ty, acc);
        __syncthreads();
        #pragma unroll
        for (int r = 0; r < 6; r++){
            float2 v0 = up2(acc[2*r]), v1 = up2(acc[2*r+1]);
            *(float4*)(xs + (ty*6+r)*H + 4*tx) =
                make_float4(gelu(v0.x+b1v.x), gelu(v0.y+b1v.y),
                            gelu(v1.x+b1v.z), gelu(v1.y+b1v.w));
        }
        __syncthreads();

        #pragma unroll
        for (int q = 0; q < 12; q++) acc[q] = 0ull;
        mm48(xs, ws2, tx, ty, acc);
        __syncthreads();                        // xs free for next iteration

        #pragma unroll
        for (int r = 0; r < 6; r++){
            int m = ty*6 + r;
            float4 e = *(const float4*)(edge_h + ((size_t)i*KN + m)*H + 4*tx);
            float2 v0 = up2(acc[2*r]), v1 = up2(acc[2*r+1]);
            float x0 = e.x+v0.x+b2v.x, x1 = e.y+v0.y+b2v.y;
            float x2 = e.z+v1.x+b2v.z, x3 = e.w+v1.y+b2v.w;
            float s = x0+x1+x2+x3, q = x0*x0+x1*x1+x2*x2+x3*x3;
            #pragma unroll
            for (int off = 16; off; off >>= 1){
                s += __shfl_xor_sync(0xffffffffu, s, off);
                q += __shfl_xor_sync(0xffffffffu, q, off);
            }
            float mean = s * (1.0f/H);
            float rstd = rsqrtf(q*(1.0f/H) - mean*mean + 1e-5f);
            *(float4*)(out_edge + ((size_t)i*KN + m)*H + 4*tx) =
                make_float4((x0-mean)*rstd*lg.x+lb.x, (x1-mean)*rstd*lg.y+lb.y,
                            (x2-mean)*rstd*lg.z+lb.z, (x3-mean)*rstd*lg.w+lb.w);
        }
    }
}

// ---------------------------------------------------------------------------
extern "C" void kernel_launch(void* const* d_in, const int* in_sizes, int n_in,
                              void* d_out, int out_size){
    const float* node_h  = (const float*)d_in[0];
    const float* edge_h  = (const float*)d_in[1];
    const float* msg_w0  = (const float*)d_in[2];
    const float* msg_b0  = (const float*)d_in[3];
    const float* msg_w1  = (const float*)d_in[4];
    const float* msg_b1  = (const float*)d_in[5];
    const float* msg_w2  = (const float*)d_in[6];
    const float* msg_b2  = (const float*)d_in[7];
    const float* ff_w0   = (const float*)d_in[8];
    const float* ff_b0   = (const float*)d_in[9];
    const float* ff_w1   = (const float*)d_in[10];
    const float* ff_b1   = (const float*)d_in[11];
    const float* edge_w0 = (const float*)d_in[12];
    const float* edge_b0 = (const float*)d_in[13];
    const float* edge_w1 = (const float*)d_in[14];
    const float* edge_b1 = (const float*)d_in[15];
    const float* edge_w2 = (const float*)d_in[16];
    const float* edge_b2 = (const float*)d_in[17];
    const float* ln1_g   = (const float*)d_in[18];
    const float* ln1_b   = (const float*)d_in[19];
    const float* ln2_g   = (const float*)d_in[20];
    const float* ln2_b   = (const float*)d_in[21];
    const float* lne_g   = (const float*)d_in[22];
    const float* lne_b   = (const float*)d_in[23];
    const int*   edge_idx= (const int*)  d_in[24];

    float* out_node = (float*)d_out;                 // [12000,128]
    float* out_edge = out_node + (size_t)RES*H;      // [12000,48,128]

    const int SMEM_BIG   = (3*HH + TILE_FLOATS) * 4; // 221184 B
    const int SMEM_SMALL = (HH + TILE_FLOATS) * 4;   //  90112 B
    cudaFuncSetAttribute(proj_kernel, cudaFuncAttributeMaxDynamicSharedMemorySize, SMEM_SMALL);
    cudaFuncSetAttribute(ff1_kernel,  cudaFuncAttributeMaxDynamicSharedMemorySize, SMEM_SMALL);
    cudaFuncSetAttribute(ff2_kernel,  cudaFuncAttributeMaxDynamicSharedMemorySize, SMEM_SMALL);
    cudaFuncSetAttribute(msg_kernel,  cudaFuncAttributeMaxDynamicSharedMemorySize, SMEM_BIG);
    cudaFuncSetAttribute(edge_kernel, cudaFuncAttributeMaxDynamicSharedMemorySize, SMEM_BIG);

    int dev = 0, nsm = 148;
    if (cudaGetDevice(&dev) == cudaSuccess){
        int v = 0;
        if (cudaDeviceGetAttribute(&v, cudaDevAttrMultiProcessorCount, dev) == cudaSuccess && v > 0)
            nsm = v;
    }

    const int NBLK = RES / KN;   // 250, exact

    // message stage projections: PA1 = node@W0a + b0, PB1 = node@W0b
    proj_kernel<<<NBLK, NTHREADS, SMEM_SMALL>>>(node_h, msg_w0,           msg_b0, 0);
    proj_kernel<<<NBLK, NTHREADS, SMEM_SMALL>>>(node_h, msg_w0 + 128*H,   nullptr, 1);
    // fused message MLP + k-sum + LN1 -> NODE1
    msg_kernel<<<nsm, NTHREADS, SMEM_BIG>>>(node_h, edge_h, msg_w0 + 256*H,
                                            msg_w1, msg_b1, msg_w2, msg_b2,
                                            ln1_g, ln1_b, edge_idx);
    // feed-forward + LN2 -> node2 (d_out)
    ff1_kernel<<<dim3(NBLK, 4), NTHREADS, SMEM_SMALL>>>(ff_w0, ff_b0);
    ff2_kernel<<<NBLK, NTHREADS, SMEM_SMALL>>>(ff_w1, ff_b1, ln2_g, ln2_b, out_node);
    // edge stage projections from refreshed node states
    proj_kernel<<<NBLK, NTHREADS, SMEM_SMALL>>>(out_node, edge_w0,         edge_b0, 2);
    proj_kernel<<<NBLK, NTHREADS, SMEM_SMALL>>>(out_node, edge_w0 + 128*H, nullptr, 3);
    // fused edge MLP + residual + LNe -> d_out (edge section)
    edge_kernel<<<nsm, NTHREADS, SMEM_BIG>>>(edge_h, edge_w0 + 256*H,
                                             edge_w1, edge_b1, edge_w2, edge_b2,
                                             lne_g, lne_b, edge_idx, out_edge);
    (void)in_sizes; (void)n_in; (void)out_size;
}

// round 6
// speedup vs baseline: 1.6449x; 1.6449x over previous
#include <cuda_runtime.h>
#include <math.h>

// ---------------------------------------------------------------------------
// EncoderLayer: RES=12000 residues, K=48 neighbors, H=128 hidden.
//
// Decomposition:
//   concat(h_i,h_j,e) @ W0  ==  h_i@W0a + h_j@W0b + e@W0c
//   and h_j@W0b == (node@W0b)[edge_idx]   (project-then-gather)
//
// R6: R4 contiguous-column mm48 layout kept (crossbar 44 cyc/SM/k < 48 fma),
//     register blowup fixed: launch_bounds(.,1) lifts the reg cap, outer k
//     loop not unrolled, per-step w loads -> ~60 live regs, FFMA2 pairs intact.
// ---------------------------------------------------------------------------

#define RES   12000
#define KN    48
#define H     128
#define HH    (H*H)            // 16384 floats
#define TILE_FLOATS (KN*H)     // 6144 floats
#define NTHREADS 256

typedef unsigned long long u64;

// Scratch (no cudaMalloc allowed; __device__ globals are the sanctioned path)
__device__ float g_PA1[RES*H];
__device__ float g_PB1[RES*H];
__device__ float g_PA2[RES*H];
__device__ float g_PB2[RES*H];
__device__ float g_NODE1[RES*H];
__device__ float g_FFH[(size_t)RES*4*H];

// ---------------- packed f32x2 helpers (Blackwell sm_103a) -----------------
__device__ __forceinline__ u64 pk2(float x){
    u64 r; asm("mov.b64 %0, {%1, %1};" : "=l"(r) : "f"(x)); return r;
}
__device__ __forceinline__ u64 pk(float lo, float hi){
    u64 r; asm("mov.b64 %0, {%1, %2};" : "=l"(r) : "f"(lo), "f"(hi)); return r;
}
__device__ __forceinline__ u64 fma2(u64 a, u64 b, u64 c){
    u64 d; asm("fma.rn.f32x2 %0, %1, %2, %3;" : "=l"(d) : "l"(a), "l"(b), "l"(c)); return d;
}
__device__ __forceinline__ float2 up2(u64 v){
    float lo, hi; asm("mov.b64 {%0, %1}, %2;" : "=f"(lo), "=f"(hi) : "l"(v));
    return make_float2(lo, hi);
}
__device__ __forceinline__ float gelu(float x){
    // exact-erf GELU (reference uses approximate=False)
    return 0.5f * x * (1.0f + erff(x * 0.7071067811865475f));
}

// 48x128 += 48x128 @ 128x128, xs/ws in smem (both natural row-major).
// thread (tx,ty): rows m = ty*6 .. ty*6+5 ; cols 4tx..4tx+3
// acc[2r] = col pair (4tx,4tx+1) of row r ; acc[2r+1] = pair (4tx+2,4tx+3)
__device__ __forceinline__ void mm48(const float* __restrict__ xs,
                                     const float* __restrict__ ws,
                                     int tx, int ty, u64 acc[12]){
    const float* xr = xs + ty*6*H;
    const float4* wp = (const float4*)ws + tx;   // + k*(H/4) per k-row
    #pragma unroll 1
    for (int k = 0; k < H; k += 4){
        // x: one LDS.128 broadcast per row covers 4 k-steps
        float4 xv0 = *(const float4*)(xr + 0*H + k);
        float4 xv1 = *(const float4*)(xr + 1*H + k);
        float4 xv2 = *(const float4*)(xr + 2*H + k);
        float4 xv3 = *(const float4*)(xr + 3*H + k);
        float4 xv4 = *(const float4*)(xr + 4*H + k);
        float4 xv5 = *(const float4*)(xr + 5*H + k);
        float4 wk;

#define MM48_STEP(COMP)                                                        \
        {                                                                      \
            u64 wl = pk(wk.x, wk.y), wh = pk(wk.z, wk.w);                      \
            u64 a0 = pk2(xv0.COMP); acc[0]  = fma2(a0, wl, acc[0]);            \
                                    acc[1]  = fma2(a0, wh, acc[1]);            \
            u64 a1 = pk2(xv1.COMP); acc[2]  = fma2(a1, wl, acc[2]);            \
                                    acc[3]  = fma2(a1, wh, acc[3]);            \
            u64 a2 = pk2(xv2.COMP); acc[4]  = fma2(a2, wl, acc[4]);            \
                                    acc[5]  = fma2(a2, wh, acc[5]);            \
            u64 a3 = pk2(xv3.COMP); acc[6]  = fma2(a3, wl, acc[6]);            \
                                    acc[7]  = fma2(a3, wh, acc[7]);            \
            u64 a4 = pk2(xv4.COMP); acc[8]  = fma2(a4, wl, acc[8]);            \
                                    acc[9]  = fma2(a4, wh, acc[9]);            \
            u64 a5 = pk2(xv5.COMP); acc[10] = fma2(a5, wl, acc[10]);           \
                                    acc[11] = fma2(a5, wh, acc[11]);           \
        }
        wk = wp[(k+0)*(H/4)];
        MM48_STEP(x)
        wk = wp[(k+1)*(H/4)];
        MM48_STEP(y)
        wk = wp[(k+2)*(H/4)];
        MM48_STEP(z)
        wk = wp[(k+3)*(H/4)];
        MM48_STEP(w)
#undef MM48_STEP
    }
}

__device__ __forceinline__ void copy16k(float* dst, const float* src, int tid){
    const float4* s = (const float4*)src; float4* d = (float4*)dst;
    #pragma unroll 4
    for (int i = tid; i < HH/4; i += NTHREADS) d[i] = s[i];
}
__device__ __forceinline__ void copytile(float* dst, const float* src, int tid){
    const float4* s = (const float4*)src; float4* d = (float4*)dst;
    #pragma unroll
    for (int i = tid; i < TILE_FLOATS/4; i += NTHREADS) d[i] = s[i];
}

// ------------------------- proj: out = src@W (+bias) -----------------------
__global__ void __launch_bounds__(NTHREADS, 1)
proj_kernel(const float* __restrict__ src, const float* __restrict__ w,
            const float* __restrict__ bias, int sel){
    extern __shared__ float sm[];
    float* ws = sm; float* xs = sm + HH;
    int tid = threadIdx.x, tx = tid & 31, ty = tid >> 5;
    copy16k(ws, w, tid);
    copytile(xs, src + (size_t)blockIdx.x*TILE_FLOATS, tid);
    __syncthreads();
    u64 acc[12];
    #pragma unroll
    for (int q = 0; q < 12; q++) acc[q] = 0ull;
    mm48(xs, ws, tx, ty, acc);
    float4 bv = make_float4(0.f,0.f,0.f,0.f);
    if (bias) bv = *(const float4*)(bias + 4*tx);
    float* outp = (sel==0) ? g_PA1 : (sel==1) ? g_PB1 : (sel==2) ? g_PA2 : g_PB2;
    int base = blockIdx.x * KN;
    #pragma unroll
    for (int r = 0; r < 6; r++){
        int m = ty*6 + r;
        float2 v0 = up2(acc[2*r]), v1 = up2(acc[2*r+1]);
        *(float4*)(outp + (size_t)(base+m)*H + 4*tx) =
            make_float4(v0.x+bv.x, v0.y+bv.y, v1.x+bv.z, v1.y+bv.w);
    }
}

// --------------------- message pass + k-sum + LN1 --------------------------
__global__ void __launch_bounds__(NTHREADS, 1)
msg_kernel(const float* __restrict__ node_h, const float* __restrict__ edge_h,
           const float* __restrict__ w0c, const float* __restrict__ w1,
           const float* __restrict__ b1,  const float* __restrict__ w2,
           const float* __restrict__ b2,  const float* __restrict__ ln1_g,
           const float* __restrict__ ln1_b, const int* __restrict__ edge_idx){
    extern __shared__ float sm[];
    float* ws0 = sm; float* ws1 = sm + HH; float* ws2 = sm + 2*HH;
    float* xs  = sm + 3*HH;                       // TILE_FLOATS, also reduction scratch
    int tid = threadIdx.x, tx = tid & 31, ty = tid >> 5;

    copy16k(ws0, w0c, tid);
    copy16k(ws1, w1, tid);
    copy16k(ws2, w2, tid);
    float4 b1v = *(const float4*)(b1 + 4*tx);
    float lg=0.f, lb=0.f, b2t=0.f;
    if (tid < H){ lg=ln1_g[tid]; lb=ln1_b[tid]; b2t=b2[tid]; }
    __syncthreads();

    for (int i = blockIdx.x; i < RES; i += gridDim.x){
        copytile(xs, edge_h + (size_t)i*TILE_FLOATS, tid);
        int jr[6];
        #pragma unroll
        for (int r = 0; r < 6; r++) jr[r] = edge_idx[i*KN + ty*6 + r];
        __syncthreads();

        // layer 0: y0 = e@W0c + PA1[i] + PB1[j] ; x1 = gelu(y0)
        u64 acc[12];
        #pragma unroll
        for (int q = 0; q < 12; q++) acc[q] = 0ull;
        mm48(xs, ws0, tx, ty, acc);
        float4 pa = *(const float4*)(g_PA1 + (size_t)i*H + 4*tx);
        __syncthreads();
        #pragma unroll
        for (int r = 0; r < 6; r++){
            float4 pb = *(const float4*)(g_PB1 + (size_t)jr[r]*H + 4*tx);
            float2 v0 = up2(acc[2*r]), v1 = up2(acc[2*r+1]);
            *(float4*)(xs + (ty*6+r)*H + 4*tx) =
                make_float4(gelu(v0.x+pa.x+pb.x), gelu(v0.y+pa.y+pb.y),
                            gelu(v1.x+pa.z+pb.z), gelu(v1.y+pa.w+pb.w));
        }
        __syncthreads();

        // layer 1: x2 = gelu(x1@W1 + b1)
        #pragma unroll
        for (int q = 0; q < 12; q++) acc[q] = 0ull;
        mm48(xs, ws1, tx, ty, acc);
        __syncthreads();
        #pragma unroll
        for (int r = 0; r < 6; r++){
            float2 v0 = up2(acc[2*r]), v1 = up2(acc[2*r+1]);
            *(float4*)(xs + (ty*6+r)*H + 4*tx) =
                make_float4(gelu(v0.x+b1v.x), gelu(v0.y+b1v.y),
                            gelu(v1.x+b1v.z), gelu(v1.y+b1v.w));
        }
        __syncthreads();

        // layer 2: y2 = x2@W2 (+b2 folded into the k-sum as 48*b2)
        #pragma unroll
        for (int q = 0; q < 12; q++) acc[q] = 0ull;
        mm48(xs, ws2, tx, ty, acc);
        float c0=0.f, c1=0.f, c2=0.f, c3=0.f;
        #pragma unroll
        for (int r = 0; r < 6; r++){
            float2 v0 = up2(acc[2*r]), v1 = up2(acc[2*r+1]);
            c0 += v0.x; c1 += v0.y; c2 += v1.x; c3 += v1.y;
        }
        __syncthreads();                       // xs reads done -> reuse as scratch
        *(float4*)(xs + ty*H + 4*tx) = make_float4(c0, c1, c2, c3);
        __syncthreads();
        float v = 0.f;
        if (tid < H){
            float s = 0.f;
            #pragma unroll
            for (int t = 0; t < 8; t++) s += xs[t*H + tid];
            v = node_h[(size_t)i*H + tid] + s + 48.0f*b2t;
            xs[1024 + tid] = v;
        }
        __syncthreads();
        if (tid < 32){
            float s = 0.f, q = 0.f;
            #pragma unroll
            for (int g = 0; g < 4; g++){ float t = xs[1024 + tid + 32*g]; s += t; q += t*t; }
            #pragma unroll
            for (int off = 16; off; off >>= 1){
                s += __shfl_xor_sync(0xffffffffu, s, off);
                q += __shfl_xor_sync(0xffffffffu, q, off);
            }
            if (tid == 0){
                float mean = s * (1.0f/H);
                float var  = q * (1.0f/H) - mean*mean;
                xs[1152] = mean;
                xs[1153] = rsqrtf(var + 1e-5f);
            }
        }
        __syncthreads();
        if (tid < H){
            g_NODE1[(size_t)i*H + tid] = (v - xs[1152]) * xs[1153] * lg + lb;
        }
        __syncthreads();                       // protect xs before next iteration
    }
}

// ----------------------- FF part 1: FFH = gelu(N1@W0+b0) -------------------
__global__ void __launch_bounds__(NTHREADS, 1)
ff1_kernel(const float* __restrict__ w, const float* __restrict__ bias){
    extern __shared__ float sm[];
    float* ws = sm; float* xs = sm + HH;
    int tid = threadIdx.x, tx = tid & 31, ty = tid >> 5;
    int n0 = blockIdx.y * H;
    {   // strided copy: w is [128,512] row-major, take column block n0..n0+127
        float4* d = (float4*)ws;
        #pragma unroll 4
        for (int i = tid; i < HH/4; i += NTHREADS){
            int k = i >> 5, c = i & 31;
            d[i] = *(const float4*)(w + (size_t)k*(4*H) + n0 + 4*c);
        }
    }
    copytile(xs, g_NODE1 + (size_t)blockIdx.x*TILE_FLOATS, tid);
    __syncthreads();
    u64 acc[12];
    #pragma unroll
    for (int q = 0; q < 12; q++) acc[q] = 0ull;
    mm48(xs, ws, tx, ty, acc);
    float4 bv = *(const float4*)(bias + n0 + 4*tx);
    int base = blockIdx.x * KN;
    #pragma unroll
    for (int r = 0; r < 6; r++){
        int m = ty*6 + r;
        float2 v0 = up2(acc[2*r]), v1 = up2(acc[2*r+1]);
        *(float4*)(g_FFH + (size_t)(base+m)*(4*H) + n0 + 4*tx) =
            make_float4(gelu(v0.x+bv.x), gelu(v0.y+bv.y),
                        gelu(v1.x+bv.z), gelu(v1.y+bv.w));
    }
}

// ------------- FF part 2: node2 = LN2(N1 + FFH@W1 + b1) -> d_out -----------
__global__ void __launch_bounds__(NTHREADS, 1)
ff2_kernel(const float* __restrict__ w, const float* __restrict__ bias,
           const float* __restrict__ ln2_g, const float* __restrict__ ln2_b,
           float* __restrict__ out_node){
    extern __shared__ float sm[];
    float* ws = sm; float* xs = sm + HH;
    int tid = threadIdx.x, tx = tid & 31, ty = tid >> 5;
    int base = blockIdx.x * KN;
    u64 acc[12];
    #pragma unroll
    for (int q = 0; q < 12; q++) acc[q] = 0ull;
    for (int c = 0; c < 4; c++){
        copy16k(ws, w + (size_t)c*H*H, tid);      // [512,128] rows c*128..c*128+127
        {
            float4* d = (float4*)xs;
            #pragma unroll
            for (int i = tid; i < TILE_FLOATS/4; i += NTHREADS){
                int m = i >> 5, cc = i & 31;
                d[i] = *(const float4*)(g_FFH + (size_t)(base+m)*(4*H) + c*H + 4*cc);
            }
        }
        __syncthreads();
        mm48(xs, ws, tx, ty, acc);
        __syncthreads();
    }
    float4 bv = *(const float4*)(bias + 4*tx);
    float4 lg = *(const float4*)(ln2_g + 4*tx);
    float4 lb = *(const float4*)(ln2_b + 4*tx);
    #pragma unroll
    for (int r = 0; r < 6; r++){
        int row = base + ty*6 + r;
        float4 a = *(const float4*)(g_NODE1 + (size_t)row*H + 4*tx);
        float2 v0 = up2(acc[2*r]), v1 = up2(acc[2*r+1]);
        float x0 = v0.x+bv.x+a.x, x1 = v0.y+bv.y+a.y;
        float x2 = v1.x+bv.z+a.z, x3 = v1.y+bv.w+a.w;
        float s = x0+x1+x2+x3, q = x0*x0+x1*x1+x2*x2+x3*x3;
        #pragma unroll
        for (int off = 16; off; off >>= 1){
            s += __shfl_xor_sync(0xffffffffu, s, off);
            q += __shfl_xor_sync(0xffffffffu, q, off);
        }
        float mean = s * (1.0f/H);
        float rstd = rsqrtf(q*(1.0f/H) - mean*mean + 1e-5f);
        *(float4*)(out_node + (size_t)row*H + 4*tx) =
            make_float4((x0-mean)*rstd*lg.x+lb.x, (x1-mean)*rstd*lg.y+lb.y,
                        (x2-mean)*rstd*lg.z+lb.z, (x3-mean)*rstd*lg.w+lb.w);
    }
}

// -------------------- edge update + LNe -> d_out (edge) --------------------
__global__ void __launch_bounds__(NTHREADS, 1)
edge_kernel(const float* __restrict__ edge_h, const float* __restrict__ w0c,
            const float* __restrict__ w1, const float* __restrict__ b1,
            const float* __restrict__ w2, const float* __restrict__ b2,
            const float* __restrict__ lne_g, const float* __restrict__ lne_b,
            const int* __restrict__ edge_idx, float* __restrict__ out_edge){
    extern __shared__ float sm[];
    float* ws0 = sm; float* ws1 = sm + HH; float* ws2 = sm + 2*HH;
    float* xs  = sm + 3*HH;
    int tid = threadIdx.x, tx = tid & 31, ty = tid >> 5;

    copy16k(ws0, w0c, tid);
    copy16k(ws1, w1, tid);
    copy16k(ws2, w2, tid);
    float4 b1v = *(const float4*)(b1 + 4*tx);
    float4 b2v = *(const float4*)(b2 + 4*tx);
    float4 lg  = *(const float4*)(lne_g + 4*tx);
    float4 lb  = *(const float4*)(lne_b + 4*tx);
    __syncthreads();

    for (int i = blockIdx.x; i < RES; i += gridDim.x){
        copytile(xs, edge_h + (size_t)i*TILE_FLOATS, tid);
        int jr[6];
        #pragma unroll
        for (int r = 0; r < 6; r++) jr[r] = edge_idx[i*KN + ty*6 + r];
        __syncthreads();

        u64 acc[12];
        #pragma unroll
        for (int q = 0; q < 12; q++) acc[q] = 0ull;
        mm48(xs, ws0, tx, ty, acc);
        float4 pa = *(const float4*)(g_PA2 + (size_t)i*H + 4*tx);
        __syncthreads();
        #pragma unroll
        for (int r = 0; r < 6; r++){
            float4 pb = *(const float4*)(g_PB2 + (size_t)jr[r]*H + 4*tx);
            float2 v0 = up2(acc[2*r]), v1 = up2(acc[2*r+1]);
            *(float4*)(xs + (ty*6+r)*H + 4*tx) =
                make_float4(gelu(v0.x+pa.x+pb.x), gelu(v0.y+pa.y+pb.y),
                            gelu(v1.x+pa.z+pb.z), gelu(v1.y+pa.w+pb.w));
        }
        __syncthreads();

        #pragma unroll
        for (int q = 0; q < 12; q++) acc[q] = 0ull;
        mm48(xs, ws1, tx, ty, acc);
        __syncthreads();
        #pragma unroll
        for (int r = 0; r < 6; r++){
            float2 v0 = up2(acc[2*r]), v1 = up2(acc[2*r+1]);
            *(float4*)(xs + (ty*6+r)*H + 4*tx) =
                make_float4(gelu(v0.x+b1v.x), gelu(v0.y+b1v.y),
                            gelu(v1.x+b1v.z), gelu(v1.y+b1v.w));
        }
        __syncthreads();

        #pragma unroll
        for (int q = 0; q < 12; q++) acc[q] = 0ull;
        mm48(xs, ws2, tx, ty, acc);
        __syncthreads();                        // xs free for next iteration

        #pragma unroll
        for (int r = 0; r < 6; r++){
            int m = ty*6 + r;
            float4 e = *(const float4*)(edge_h + ((size_t)i*KN + m)*H + 4*tx);
            float2 v0 = up2(acc[2*r]), v1 = up2(acc[2*r+1]);
            float x0 = e.x+v0.x+b2v.x, x1 = e.y+v0.y+b2v.y;
            float x2 = e.z+v1.x+b2v.z, x3 = e.w+v1.y+b2v.w;
            float s = x0+x1+x2+x3, q = x0*x0+x1*x1+x2*x2+x3*x3;
            #pragma unroll
            for (int off = 16; off; off >>= 1){
                s += __shfl_xor_sync(0xffffffffu, s, off);
                q += __shfl_xor_sync(0xffffffffu, q, off);
            }
            float mean = s * (1.0f/H);
            float rstd = rsqrtf(q*(1.0f/H) - mean*mean + 1e-5f);
            *(float4*)(out_edge + ((size_t)i*KN + m)*H + 4*tx) =
                make_float4((x0-mean)*rstd*lg.x+lb.x, (x1-mean)*rstd*lg.y+lb.y,
                            (x2-mean)*rstd*lg.z+lb.z, (x3-mean)*rstd*lg.w+lb.w);
        }
    }
}

// ---------------------------------------------------------------------------
extern "C" void kernel_launch(void* const* d_in, const int* in_sizes, int n_in,
                              void* d_out, int out_size){
    const float* node_h  = (const float*)d_in[0];
    const float* edge_h  = (const float*)d_in[1];
    const float* msg_w0  = (const float*)d_in[2];
    const float* msg_b0  = (const float*)d_in[3];
    const float* msg_w1  = (const float*)d_in[4];
    const float* msg_b1  = (const float*)d_in[5];
    const float* msg_w2  = (const float*)d_in[6];
    const float* msg_b2  = (const float*)d_in[7];
    const float* ff_w0   = (const float*)d_in[8];
    const float* ff_b0   = (const float*)d_in[9];
    const float* ff_w1   = (const float*)d_in[10];
    const float* ff_b1   = (const float*)d_in[11];
    const float* edge_w0 = (const float*)d_in[12];
    const float* edge_b0 = (const float*)d_in[13];
    const float* edge_w1 = (const float*)d_in[14];
    const float* edge_b1 = (const float*)d_in[15];
    const float* edge_w2 = (const float*)d_in[16];
    const float* edge_b2 = (const float*)d_in[17];
    const float* ln1_g   = (const float*)d_in[18];
    const float* ln1_b   = (const float*)d_in[19];
    const float* ln2_g   = (const float*)d_in[20];
    const float* ln2_b   = (const float*)d_in[21];
    const float* lne_g   = (const float*)d_in[22];
    const float* lne_b   = (const float*)d_in[23];
    const int*   edge_idx= (const int*)  d_in[24];

    float* out_node = (float*)d_out;                 // [12000,128]
    float* out_edge = out_node + (size_t)RES*H;      // [12000,48,128]

    const int SMEM_BIG   = (3*HH + TILE_FLOATS) * 4; // 221184 B
    const int SMEM_SMALL = (HH + TILE_FLOATS) * 4;   //  90112 B
    cudaFuncSetAttribute(proj_kernel, cudaFuncAttributeMaxDynamicSharedMemorySize, SMEM_SMALL);
    cudaFuncSetAttribute(ff1_kernel,  cudaFuncAttributeMaxDynamicSharedMemorySize, SMEM_SMALL);
    cudaFuncSetAttribute(ff2_kernel,  cudaFuncAttributeMaxDynamicSharedMemorySize, SMEM_SMALL);
    cudaFuncSetAttribute(msg_kernel,  cudaFuncAttributeMaxDynamicSharedMemorySize, SMEM_BIG);
    cudaFuncSetAttribute(edge_kernel, cudaFuncAttributeMaxDynamicSharedMemorySize, SMEM_BIG);

    int dev = 0, nsm = 148;
    if (cudaGetDevice(&dev) == cudaSuccess){
        int v = 0;
        if (cudaDeviceGetAttribute(&v, cudaDevAttrMultiProcessorCount, dev) == cudaSuccess && v > 0)
            nsm = v;
    }

    const int NBLK = RES / KN;   // 250, exact

    // message stage projections: PA1 = node@W0a + b0, PB1 = node@W0b
    proj_kernel<<<NBLK, NTHREADS, SMEM_SMALL>>>(node_h, msg_w0,           msg_b0, 0);
    proj_kernel<<<NBLK, NTHREADS, SMEM_SMALL>>>(node_h, msg_w0 + 128*H,   nullptr, 1);
    // fused message MLP + k-sum + LN1 -> NODE1
    msg_kernel<<<nsm, NTHREADS, SMEM_BIG>>>(node_h, edge_h, msg_w0 + 256*H,
                                            msg_w1, msg_b1, msg_w2, msg_b2,
                                            ln1_g, ln1_b, edge_idx);
    // feed-forward + LN2 -> node2 (d_out)
    ff1_kernel<<<dim3(NBLK, 4), NTHREADS, SMEM_SMALL>>>(ff_w0, ff_b0);
    ff2_kernel<<<NBLK, NTHREADS, SMEM_SMALL>>>(ff_w1, ff_b1, ln2_g, ln2_b, out_node);
    // edge stage projections from refreshed node states
    proj_kernel<<<NBLK, NTHREADS, SMEM_SMALL>>>(out_node, edge_w0,         edge_b0, 2);
    proj_kernel<<<NBLK, NTHREADS, SMEM_SMALL>>>(out_node, edge_w0 + 128*H, nullptr, 3);
    // fused edge MLP + residual + LNe -> d_out (edge section)
    edge_kernel<<<nsm, NTHREADS, SMEM_BIG>>>(edge_h, edge_w0 + 256*H,
                                             edge_w1, edge_b1, edge_w2, edge_b2,
                                             lne_g, lne_b, edge_idx, out_edge);
    (void)in_sizes; (void)n_in; (void)out_size;
}